// round 8
// baseline (speedup 1.0000x reference)
#include <cuda_runtime.h>
#include <cuda_bf16.h>
#include <cstdint>

#define Bsz 64
#define Ssz 256
#define Isz 128
#define Hsz 128
#define UNF 6

#define SEQ_TPB 512
#define HHALF 64

// ---------------- device scratch ----------------
__device__ float2 g_rab[Hsz*Hsz];       // (a,b): a=0.5*sigma, b=-0.5*sigma*mu, [src][dst]
__device__ float  g_rcs[Hsz*Hsz];       // 0.5*softplus(w)*erev, [src][dst]
__device__ float2 g_sab[Isz*Hsz];
__device__ float  g_scs[Isz*Hsz];
__device__ float  g_numconst[Hsz];
__device__ float  g_denconst[Hsz];
__device__ float  g_cmt[Hsz];
__device__ uint32_t g_pwB[(Hsz/2)*Hsz]; // phase_W bf16x2 packed: [k2][h]
__device__ uint32_t g_saB[(Hsz/2)*Hsz]; // sa_W    bf16x2 packed: [k2][h]
__device__ float  g_numbase[Bsz*Ssz*Hsz];
__device__ float  g_denbase[Bsz*Ssz*Hsz];

// ---------------- helpers ----------------
__device__ __forceinline__ float sp(float x) { return log1pf(expf(x)); }
__device__ __forceinline__ float tanhap(float x) {
    float y; asm("tanh.approx.f32 %0, %1;" : "=f"(y) : "f"(x)); return y;
}
__device__ __forceinline__ float fabsb(float x) {
    return __int_as_float(__float_as_int(x) & 0x7fffffff);
}
__device__ __forceinline__ float2 bf2f2(uint32_t u) {
    return __bfloat1622float2(*reinterpret_cast<__nv_bfloat162*>(&u));
}
__device__ __forceinline__ uint32_t smem_u32(const void* p) {
    uint32_t a; asm("{ .reg .u64 t; cvta.to.shared.u64 t, %1; cvt.u32.u64 %0, t; }" : "=r"(a) : "l"(p));
    return a;
}
__device__ __forceinline__ void mbar_init(uint32_t mbar, uint32_t cnt) {
    asm volatile("mbarrier.init.shared.b64 [%0], %1;" :: "r"(mbar), "r"(cnt) : "memory");
}
__device__ __forceinline__ void mbar_expect_tx(uint32_t mbar, uint32_t bytes) {
    asm volatile("mbarrier.arrive.expect_tx.shared.b64 _, [%0], %1;" :: "r"(mbar), "r"(bytes) : "memory");
}
__device__ __forceinline__ void mbar_wait_cluster(uint32_t mbar, uint32_t par) {
    asm volatile(
        "{\n\t.reg .pred P;\n"
        "WL_%=:\n\t"
        "mbarrier.try_wait.parity.acquire.cluster.shared::cta.b64 P, [%0], %1, 0x989680;\n\t"
        "@!P bra WL_%=;\n\t}"
        :: "r"(mbar), "r"(par) : "memory");
}
__device__ __forceinline__ void bulk_to_peer(uint32_t dst_cluster, uint32_t src_cta,
                                             uint32_t bytes, uint32_t mbar_cluster) {
    asm volatile("fence.proxy.async.shared::cta;" ::: "memory");
    asm volatile("cp.async.bulk.shared::cluster.shared::cta.mbarrier::complete_tx::bytes "
                 "[%0], [%1], %2, [%3];"
                 :: "r"(dst_cluster), "r"(src_cta), "r"(bytes), "r"(mbar_cluster) : "memory");
}

// ---------------- kernel A: per-edge param folding ----------------
__global__ void prep_kernel(const float* __restrict__ sigma, const float* __restrict__ mu,
                            const float* __restrict__ w,     const float* __restrict__ erev,
                            const float* __restrict__ s_sigma, const float* __restrict__ s_mu,
                            const float* __restrict__ s_w,   const float* __restrict__ s_erev,
                            const float* __restrict__ input_w, const float* __restrict__ input_b)
{
    int r = blockIdx.x, h = threadIdx.x;
    if (r < Hsz) {
        int idx = r*Hsz + h;
        float a = 0.5f * sigma[idx];
        g_rab[idx] = make_float2(a, -a * mu[idx]);
        g_rcs[idx] = 0.5f * sp(w[idx]) * erev[idx];
    } else {
        int i = r - Hsz;
        int idx = i*Hsz + h;
        float a = 0.5f * s_sigma[idx];
        g_sab[idx] = make_float2(a * input_w[i], a * (input_b[i] - s_mu[idx]));
        g_scs[idx] = 0.5f * sp(s_w[idx]) * s_erev[idx];
    }
}

// ---------------- kernel A2 ----------------
__global__ void prep2_kernel(const float* __restrict__ gleak, const float* __restrict__ vleak,
                             const float* __restrict__ cm,
                             const float* __restrict__ phase_W, const float* __restrict__ sa_W)
{
    int h = threadIdx.x;
    float nc = 0.f, dc = 0.f;
    for (int j = 0; j < Hsz; j++) { float cs = g_rcs[j*Hsz + h]; nc += cs; dc += fabsf(cs); }
    for (int i = 0; i < Isz; i++) { float cs = g_scs[i*Hsz + h]; nc += cs; dc += fabsf(cs); }
    float gl  = sp(gleak[h]);
    float cmt = sp(cm[h]) * (float)UNF;
    g_numconst[h] = gl * vleak[h] + nc;
    g_denconst[h] = cmt + gl + 1e-8f + dc;
    g_cmt[h] = cmt;
    for (int k2 = 0; k2 < Hsz/2; k2++) {
        __nv_bfloat162 p, q;
        p.x = __float2bfloat16(phase_W[h*Hsz + 2*k2]);
        p.y = __float2bfloat16(phase_W[h*Hsz + 2*k2 + 1]);
        q.x = __float2bfloat16(sa_W[h*Hsz + 2*k2]);
        q.y = __float2bfloat16(sa_W[h*Hsz + 2*k2 + 1]);
        g_pwB[k2*Hsz + h] = *reinterpret_cast<uint32_t*>(&p);
        g_saB[k2*Hsz + h] = *reinterpret_cast<uint32_t*>(&q);
    }
}

// ---------------- kernel B: sensory pre-pass ----------------
__global__ __launch_bounds__(512, 1) void sens_kernel(const float* __restrict__ x)
{
    extern __shared__ float sm[];
    float2* sab = (float2*)sm;
    float*  xs  = sm + 2*Isz*Hsz;
    float*  pn  = xs + 128;
    float*  pd  = pn + 512;

    int tid = threadIdx.x;
    int h = tid & 127, g = tid >> 7;

    for (int r = tid; r < Isz*Hsz; r += 512) sab[r] = g_sab[r];

    float scs[32];
    #pragma unroll
    for (int il = 0; il < 32; il++) scs[il] = g_scs[(g*32 + il)*Hsz + h];

    float ncst = g_numconst[h], dcst = g_denconst[h];
    int s = blockIdx.x;

    for (int bb = 0; bb < 16; bb++) {
        int b = blockIdx.y * 16 + bb;
        __syncthreads();
        if (tid < Isz) xs[h] = x[(b*Ssz + s)*Isz + h];
        __syncthreads();
        float n = 0.f, d = 0.f;
        #pragma unroll
        for (int q = 0; q < 8; q++) {
            float4 x4 = *(const float4*)(xs + g*32 + 4*q);
            float xv[4] = {x4.x, x4.y, x4.z, x4.w};
            #pragma unroll
            for (int e = 0; e < 4; e++) {
                int il = 4*q + e;
                float2 p = sab[(g*32 + il)*Hsz + h];
                float t = tanhap(fmaf(p.x, xv[e], p.y));
                n = fmaf(scs[il], t, n);
                d = fmaf(fabsb(scs[il]), t, d);
            }
        }
        pn[g*Hsz + h] = n; pd[g*Hsz + h] = d;
        __syncthreads();
        if (g == 0) {
            float num = ncst + pn[h] + pn[Hsz + h] + pn[2*Hsz + h] + pn[3*Hsz + h];
            float den = dcst + pd[h] + pd[Hsz + h] + pd[2*Hsz + h] + pd[3*Hsz + h];
            int o = (b*Ssz + s)*Hsz + h;
            g_numbase[o] = num;
            g_denbase[o] = den;
        }
    }
}

// ---------------- smem byte offsets for seq kernel ----------------
#define OFF_PWB    0                      // 64*128*4 = 32768
#define OFF_SAB    32768                  // + 32768 = 65536
#define OFF_VFULL  65536                  // 2 slots * 128 * 4 = 1024
#define OFF_VFIN   66560                  // 512
#define OFF_PPH    67072                  // 2048
#define OFF_PSA    69120                  // 2048
#define OFF_SGB    71168                  // 512
#define OFF_MBAR   71680                  // 16
#define SMEM_SEQ   71936

// ---------------- kernel C: 2-CTA cluster, bulk-copy exchange ----------------
__global__ __launch_bounds__(SEQ_TPB, 1) __cluster_dims__(2, 1, 1)
void seq_kernel(const float* __restrict__ h0, const float* __restrict__ amplitude,
                const float* __restrict__ omega, const float* __restrict__ phase_b,
                const float* __restrict__ alpha_p, const float* __restrict__ beta_p,
                float* __restrict__ out, int write_hfinal)
{
    extern __shared__ char smc[];
    uint32_t* pwb = (uint32_t*)(smc + OFF_PWB);   // [64][128] bf16x2
    uint32_t* sab = (uint32_t*)(smc + OFF_SAB);   // [64][128] bf16x2
    float* vfull  = (float*)(smc + OFF_VFULL);    // [2][128] exchange slots
    float* vfin   = (float*)(smc + OFF_VFIN);     // [128] step-final state
    float* pph    = (float*)(smc + OFF_PPH);      // [4][128]
    float* psa    = (float*)(smc + OFF_PSA);      // [4][128]
    float* sgb    = (float*)(smc + OFF_SGB);      // [128]

    uint32_t sbase = smem_u32(smc);
    uint32_t mbar  = sbase + OFF_MBAR;

    uint32_t rank; asm("mov.u32 %0, %%cluster_ctarank;" : "=r"(rank));
    uint32_t peerR = rank ^ 1u;
    int b = blockIdx.x >> 1;
    int own_base  = (int)rank * HHALF;
    int peer_base = (int)peerR * HHALF;

    int tid  = threadIdx.x;
    int lane = tid & 31;
    int warp = tid >> 5;
    int g    = lane & 7;                      // src block 0..7 (consecutive 8 srcs)
    int hl   = (warp << 2) | (lane >> 3);     // 0..63 local dst
    int habs = own_base + hl;
    int h2   = tid & 127;                     // epilogue layout: dst
    int g2   = tid >> 7;                      // epilogue layout: k quarter

    for (int idx = tid; idx < (Hsz/2)*Hsz; idx += SEQ_TPB) {
        pwb[idx] = g_pwB[idx];
        sab[idx] = g_saB[idx];
    }

    // per-thread edge params: srcs j = base + g*8 + e (CONSECUTIVE block -> float4 v loads)
    float ao[8], bo[8], cso[8], ap[8], bp[8], csp[8];
    #pragma unroll
    for (int e = 0; e < 8; e++) {
        int jo = own_base  + g*8 + e;
        int jp = peer_base + g*8 + e;
        float2 r0 = g_rab[jo*Hsz + habs];
        float2 r1 = g_rab[jp*Hsz + habs];
        ao[e] = r0.x; bo[e] = r0.y; cso[e] = g_rcs[jo*Hsz + habs];
        ap[e] = r1.x; bp[e] = r1.y; csp[e] = g_rcs[jp*Hsz + habs];
    }
    float cmt = g_cmt[habs];
    float aa2 = alpha_p[0] * amplitude[h2];
    float om2 = omega[h2];
    float pb2 = phase_b[h2];
    float bet = beta_p[0];

    if (tid < Hsz) vfin[tid] = h0[b*Hsz + tid];
    if (tid == 0) mbar_init(mbar, 1);
    __syncthreads();
    asm volatile("barrier.cluster.arrive.aligned;" ::: "memory");
    asm volatile("barrier.cluster.wait.aligned;"   ::: "memory");

    uint32_t vfull_rm, mbar_rm;
    asm("mapa.shared::cluster.u32 %0, %1, %2;" : "=r"(vfull_rm) : "r"(sbase + OFF_VFULL), "r"(peerR));
    asm("mapa.shared::cluster.u32 %0, %1, %2;" : "=r"(mbar_rm)  : "r"(sbase + OFF_MBAR),  "r"(peerR));

    if (tid == 0) mbar_expect_tx(mbar, 256);

    uint32_t rc = 0;
    float nb = g_numbase[(b*Ssz)*Hsz + habs];
    float db = g_denbase[(b*Ssz)*Hsz + habs];
    float v;

    // one edge-block accumulation: 2x float4 loads + 8 tanh + FMAs
    #define EDGE_HALF(VPTR, BASE, A, B_, CS, N, D)                                  \
        {                                                                           \
            float4 wa = *(const float4*)((VPTR) + (BASE) + g*8);                    \
            float4 wb = *(const float4*)((VPTR) + (BASE) + g*8 + 4);                \
            float vv[8] = {wa.x, wa.y, wa.z, wa.w, wb.x, wb.y, wb.z, wb.w};         \
            _Pragma("unroll")                                                       \
            for (int e = 0; e < 8; e++) {                                           \
                float t = tanhap(fmaf((A)[e], vv[e], (B_)[e]));                     \
                N = fmaf((CS)[e], t, N);                                            \
                D = fmaf(fabsb((CS)[e]), t, D);                                     \
            }                                                                       \
        }

    #define REDUCE_ND(N, D)                                                         \
        N += __shfl_xor_sync(0xffffffffu, N, 1);                                    \
        D += __shfl_xor_sync(0xffffffffu, D, 1);                                    \
        N += __shfl_xor_sync(0xffffffffu, N, 2);                                    \
        D += __shfl_xor_sync(0xffffffffu, D, 2);                                    \
        N += __shfl_xor_sync(0xffffffffu, N, 4);                                    \
        D += __shfl_xor_sync(0xffffffffu, D, 4);

    for (int s = 0; s < Ssz; s++) {
        float nb_n = 0.f, db_n = 0.f;
        if (s + 1 < Ssz) {
            nb_n = g_numbase[(b*Ssz + s + 1)*Hsz + habs];
            db_n = g_denbase[(b*Ssz + s + 1)*Hsz + habs];
        }

        // ---- unfold 0: fully local ----
        v = vfin[habs];
        {
            float n = 0.f, d = 0.f;
            EDGE_HALF(vfin, own_base,  ao, bo, cso, n, d)
            EDGE_HALF(vfin, peer_base, ap, bp, csp, n, d)
            REDUCE_ND(n, d)
            v = __fdividef(fmaf(cmt, v, nb + n), db + d);
        }
        if (g == 0) vfull[0*Hsz + habs] = v;
        __syncthreads();
        if (tid == 0)
            bulk_to_peer(vfull_rm + (uint32_t)own_base*4u,
                         sbase + OFF_VFULL + (uint32_t)own_base*4u, 256u, mbar_rm);

        // ---- unfolds 1..5 (FULLY UNROLLED: slots compile-time) ----
        #pragma unroll
        for (int u = 1; u < UNF; u++) {
            const int rslot = (u - 1) & 1;
            const int wslot = u & 1;
            const float* vf = vfull + rslot*Hsz;
            float n = 0.f, d = 0.f;
            EDGE_HALF(vf, own_base, ao, bo, cso, n, d)
            mbar_wait_cluster(mbar, rc & 1u); rc++;
            if (tid == 0) mbar_expect_tx(mbar, 256);
            EDGE_HALF(vf, peer_base, ap, bp, csp, n, d)
            REDUCE_ND(n, d)
            v = __fdividef(fmaf(cmt, v, nb + n), db + d);
            if (g == 0) vfull[wslot*Hsz + habs] = v;
            __syncthreads();
            if (tid == 0)
                bulk_to_peer(vfull_rm + (uint32_t)(wslot*512 + own_base*4),
                             sbase + OFF_VFULL + (uint32_t)(wslot*512 + own_base*4),
                             256u, mbar_rm);
        }

        // ---- epilogue: redundant full-h compute (bf16 weights) ----
        mbar_wait_cluster(mbar, rc & 1u); rc++;
        if (tid == 0) mbar_expect_tx(mbar, 256);
        const float* v6 = vfull + 1*Hsz;              // slot (UNF-1)&1 = 1
        const float2* v6f2 = (const float2*)v6;

        {
            float php = 0.f;
            #pragma unroll 8
            for (int i = 0; i < 16; i++) {
                int k2 = g2*16 + i;
                float2 wv = bf2f2(pwb[k2*Hsz + h2]);
                float2 v2 = v6f2[k2];
                php = fmaf(wv.x, v2.x, fmaf(wv.y, v2.y, php));
            }
            pph[g2*Hsz + h2] = php;
        }
        __syncthreads();
        float phi = pph[h2] + pph[Hsz + h2] + pph[2*Hsz + h2] + pph[3*Hsz + h2] + pb2;
        float vp  = v6[h2] + aa2 * __sinf(fmaf(om2, (float)s, phi));
        float sg  = fmaf(0.5f, tanhap(0.5f * vp), 0.5f);
        sgb[h2] = sg;                                  // 4 same-value writers, benign
        __syncthreads();
        {
            const float2* sgf2 = (const float2*)sgb;
            float accp = 0.f;
            #pragma unroll 8
            for (int i = 0; i < 16; i++) {
                int k2 = g2*16 + i;
                float2 wv = bf2f2(sab[k2*Hsz + h2]);
                float2 s2 = sgf2[k2];
                accp = fmaf(wv.x, s2.x, fmaf(wv.y, s2.y, accp));
            }
            psa[g2*Hsz + h2] = accp;
        }
        __syncthreads();
        if (g2 == 0) {
            float acc = psa[h2] + psa[Hsz + h2] + psa[2*Hsz + h2] + psa[3*Hsz + h2];
            float vfl = fmaf(bet, acc, vp);
            if (rank == 0) out[(b*Ssz + s)*Hsz + h2] = vfl;   // dedupe redundant STG
            vfin[h2] = vfl;
        }
        __syncthreads();

        nb = nb_n; db = db_n;
    }

    if (write_hfinal && g2 == 0 && rank == 0)
        out[Bsz*Ssz*Hsz + b*Hsz + h2] = vfin[h2];

    asm volatile("barrier.cluster.arrive.aligned;" ::: "memory");
    asm volatile("barrier.cluster.wait.aligned;"   ::: "memory");

    #undef EDGE_HALF
    #undef REDUCE_ND
}

// ---------------- launch ----------------
extern "C" void kernel_launch(void* const* d_in, const int* in_sizes, int n_in,
                              void* d_out, int out_size)
{
    const float* x        = (const float*)d_in[0];
    const float* h0       = (const float*)d_in[1];
    const float* input_w  = (const float*)d_in[2];
    const float* input_b  = (const float*)d_in[3];
    const float* gleak    = (const float*)d_in[4];
    const float* vleak    = (const float*)d_in[5];
    const float* cm       = (const float*)d_in[6];
    const float* sigma    = (const float*)d_in[7];
    const float* mu       = (const float*)d_in[8];
    const float* w        = (const float*)d_in[9];
    const float* erev     = (const float*)d_in[10];
    const float* s_sigma  = (const float*)d_in[11];
    const float* s_mu     = (const float*)d_in[12];
    const float* s_w      = (const float*)d_in[13];
    const float* s_erev   = (const float*)d_in[14];
    const float* amplitude= (const float*)d_in[15];
    const float* omega    = (const float*)d_in[16];
    const float* phase_W  = (const float*)d_in[17];
    const float* phase_b  = (const float*)d_in[18];
    const float* alpha    = (const float*)d_in[19];
    const float* sa_W     = (const float*)d_in[20];
    const float* beta     = (const float*)d_in[21];
    float* out = (float*)d_out;

    const int smem_sens = 2*Isz*Hsz*4 + (128 + 512 + 512)*4;
    cudaFuncSetAttribute(sens_kernel, cudaFuncAttributeMaxDynamicSharedMemorySize, smem_sens);
    cudaFuncSetAttribute(seq_kernel,  cudaFuncAttributeMaxDynamicSharedMemorySize, SMEM_SEQ);

    prep_kernel<<<Hsz + Isz, Hsz>>>(sigma, mu, w, erev, s_sigma, s_mu, s_w, s_erev, input_w, input_b);
    prep2_kernel<<<1, Hsz>>>(gleak, vleak, cm, phase_W, sa_W);

    dim3 gb(Ssz, Bsz/16);
    sens_kernel<<<gb, 512, smem_sens>>>(x);

    int whf = (out_size >= Bsz*Ssz*Hsz + Bsz*Hsz) ? 1 : 0;
    seq_kernel<<<Bsz*2, SEQ_TPB, SMEM_SEQ>>>(h0, amplitude, omega, phase_b, alpha, beta, out, whf);
}

// round 9
// speedup vs baseline: 1.0376x; 1.0376x over previous
#include <cuda_runtime.h>
#include <cuda_bf16.h>
#include <cstdint>

#define Bsz 64
#define Ssz 256
#define Isz 128
#define Hsz 128
#define UNF 6

#define SEQ_TPB 512
#define HHALF 64
#define SSTR 136    // floats per sensory row (bank-engineered)

// ---------------- device scratch ----------------
__device__ float2 g_rab[Hsz*Hsz];       // (a,b): a=0.5*sigma, b=-0.5*sigma*mu, [src][dst]
__device__ float  g_rcs[Hsz*Hsz];       // 0.5*softplus(w)*erev, [src][dst]
__device__ float2 g_sab[Isz*Hsz];       // sensory (a',b') with input affine folded, [i][h]
__device__ float  g_scs[Isz*Hsz];       // sensory signed weight, [i][h]
__device__ float  g_numconst[Hsz];
__device__ float  g_denconst[Hsz];
__device__ float  g_cmt[Hsz];
__device__ uint32_t g_pwB[(Hsz/2)*Hsz]; // phase_W bf16x2 packed: [k2][h]
__device__ uint32_t g_saB[(Hsz/2)*Hsz]; // sa_W    bf16x2 packed: [k2][h]

// ---------------- helpers ----------------
__device__ __forceinline__ float sp(float x) { return log1pf(expf(x)); }
__device__ __forceinline__ float tanhap(float x) {
    float y; asm("tanh.approx.f32 %0, %1;" : "=f"(y) : "f"(x)); return y;
}
__device__ __forceinline__ float fabsb(float x) {
    return __int_as_float(__float_as_int(x) & 0x7fffffff);
}
__device__ __forceinline__ float2 bf2f2(uint32_t u) {
    return __bfloat1622float2(*reinterpret_cast<__nv_bfloat162*>(&u));
}
__device__ __forceinline__ uint32_t smem_u32(const void* p) {
    uint32_t a; asm("{ .reg .u64 t; cvta.to.shared.u64 t, %1; cvt.u32.u64 %0, t; }" : "=r"(a) : "l"(p));
    return a;
}
__device__ __forceinline__ void mbar_init(uint32_t mbar, uint32_t cnt) {
    asm volatile("mbarrier.init.shared.b64 [%0], %1;" :: "r"(mbar), "r"(cnt) : "memory");
}
__device__ __forceinline__ void mbar_expect_tx(uint32_t mbar, uint32_t bytes) {
    asm volatile("mbarrier.arrive.expect_tx.shared.b64 _, [%0], %1;" :: "r"(mbar), "r"(bytes) : "memory");
}
__device__ __forceinline__ void mbar_wait_cluster(uint32_t mbar, uint32_t par) {
    asm volatile(
        "{\n\t.reg .pred P;\n"
        "WL_%=:\n\t"
        "mbarrier.try_wait.parity.acquire.cluster.shared::cta.b64 P, [%0], %1, 0x989680;\n\t"
        "@!P bra WL_%=;\n\t}"
        :: "r"(mbar), "r"(par) : "memory");
}
__device__ __forceinline__ void bulk_to_peer(uint32_t dst_cluster, uint32_t src_cta,
                                             uint32_t bytes, uint32_t mbar_cluster) {
    asm volatile("fence.proxy.async.shared::cta;" ::: "memory");
    asm volatile("cp.async.bulk.shared::cluster.shared::cta.mbarrier::complete_tx::bytes "
                 "[%0], [%1], %2, [%3];"
                 :: "r"(dst_cluster), "r"(src_cta), "r"(bytes), "r"(mbar_cluster) : "memory");
}

// ---------------- kernel A: per-edge param folding ----------------
__global__ void prep_kernel(const float* __restrict__ sigma, const float* __restrict__ mu,
                            const float* __restrict__ w,     const float* __restrict__ erev,
                            const float* __restrict__ s_sigma, const float* __restrict__ s_mu,
                            const float* __restrict__ s_w,   const float* __restrict__ s_erev,
                            const float* __restrict__ input_w, const float* __restrict__ input_b)
{
    int r = blockIdx.x, h = threadIdx.x;
    if (r < Hsz) {
        int idx = r*Hsz + h;
        float a = 0.5f * sigma[idx];
        g_rab[idx] = make_float2(a, -a * mu[idx]);
        g_rcs[idx] = 0.5f * sp(w[idx]) * erev[idx];
    } else {
        int i = r - Hsz;
        int idx = i*Hsz + h;
        float a = 0.5f * s_sigma[idx];
        g_sab[idx] = make_float2(a * input_w[i], a * (input_b[i] - s_mu[idx]));
        g_scs[idx] = 0.5f * sp(s_w[idx]) * s_erev[idx];
    }
}

// ---------------- kernel A2 ----------------
__global__ void prep2_kernel(const float* __restrict__ gleak, const float* __restrict__ vleak,
                             const float* __restrict__ cm,
                             const float* __restrict__ phase_W, const float* __restrict__ sa_W)
{
    int h = threadIdx.x;
    float nc = 0.f, dc = 0.f;
    for (int j = 0; j < Hsz; j++) { float cs = g_rcs[j*Hsz + h]; nc += cs; dc += fabsf(cs); }
    for (int i = 0; i < Isz; i++) { float cs = g_scs[i*Hsz + h]; nc += cs; dc += fabsf(cs); }
    float gl  = sp(gleak[h]);
    float cmt = sp(cm[h]) * (float)UNF;
    g_numconst[h] = gl * vleak[h] + nc;
    g_denconst[h] = cmt + gl + 1e-8f + dc;
    g_cmt[h] = cmt;
    for (int k2 = 0; k2 < Hsz/2; k2++) {
        __nv_bfloat162 p, q;
        p.x = __float2bfloat16(phase_W[h*Hsz + 2*k2]);
        p.y = __float2bfloat16(phase_W[h*Hsz + 2*k2 + 1]);
        q.x = __float2bfloat16(sa_W[h*Hsz + 2*k2]);
        q.y = __float2bfloat16(sa_W[h*Hsz + 2*k2 + 1]);
        g_pwB[k2*Hsz + h] = *reinterpret_cast<uint32_t*>(&p);
        g_saB[k2*Hsz + h] = *reinterpret_cast<uint32_t*>(&q);
    }
}

// ---------------- smem byte offsets for seq kernel ----------------
#define OFF_PWB    0                       // 32768
#define OFF_SAB    32768                   // 32768 -> 65536
#define OFF_SSA    65536                   // 64*136*4 = 34816 -> 100352
#define OFF_SSB    100352                  // 34816 -> 135168
#define OFF_SSC    135168                  // 34816 -> 169984
#define OFF_VFULL  169984                  // 2*128*4 = 1024 -> 171008
#define OFF_VFIN   171008                  // 512 -> 171520
#define OFF_PPH    171520                  // 2048 -> 173568
#define OFF_PSA    173568                  // 2048 -> 175616
#define OFF_SGB    175616                  // 512 -> 176128
#define OFF_XBUF   176128                  // 2*128*4 = 1024 -> 177152
#define OFF_MBAR   177152                  // 16
#define SMEM_SEQ   177280

// ---------------- kernel C: fused scan — sensory folded into stall windows ----------------
__global__ __launch_bounds__(SEQ_TPB, 1) __cluster_dims__(2, 1, 1)
void seq_kernel(const float* __restrict__ x, const float* __restrict__ h0,
                const float* __restrict__ amplitude, const float* __restrict__ omega,
                const float* __restrict__ phase_b, const float* __restrict__ alpha_p,
                const float* __restrict__ beta_p,
                float* __restrict__ out, int write_hfinal)
{
    extern __shared__ char smc[];
    uint32_t* pwb = (uint32_t*)(smc + OFF_PWB);   // [64][128] bf16x2
    uint32_t* sab = (uint32_t*)(smc + OFF_SAB);   // [64][128] bf16x2
    float* ssa    = (float*)(smc + OFF_SSA);      // [64][SSTR] sensory a'
    float* ssb    = (float*)(smc + OFF_SSB);      // [64][SSTR] sensory b'
    float* ssc    = (float*)(smc + OFF_SSC);      // [64][SSTR] sensory cs
    float* vfull  = (float*)(smc + OFF_VFULL);    // [2][128] exchange slots
    float* vfin   = (float*)(smc + OFF_VFIN);     // [128]
    float* pph    = (float*)(smc + OFF_PPH);      // [4][128]
    float* psa    = (float*)(smc + OFF_PSA);      // [4][128]
    float* sgb    = (float*)(smc + OFF_SGB);      // [128]
    float* xbuf   = (float*)(smc + OFF_XBUF);     // [2][128]

    uint32_t sbase = smem_u32(smc);
    uint32_t mbar  = sbase + OFF_MBAR;

    uint32_t rank; asm("mov.u32 %0, %%cluster_ctarank;" : "=r"(rank));
    uint32_t peerR = rank ^ 1u;
    int b = blockIdx.x >> 1;
    int own_base  = (int)rank * HHALF;
    int peer_base = (int)peerR * HHALF;

    int tid  = threadIdx.x;
    int lane = tid & 31;
    int warp = tid >> 5;
    int g    = lane & 7;                      // src subgroup 0..7 (R7 scattered layout)
    int hl   = (warp << 2) | (lane >> 3);     // 0..63 local dst
    int habs = own_base + hl;
    int h2   = tid & 127;                     // epilogue layout: dst
    int g2   = tid >> 7;                      // epilogue layout: k quarter

    // preload epilogue weights (bf16x2, [k2][h])
    for (int idx = tid; idx < (Hsz/2)*Hsz; idx += SEQ_TPB) {
        pwb[idx] = g_pwB[idx];
        sab[idx] = g_saB[idx];
    }
    // preload sensory params for own dst columns: [hl][i], stride SSTR
    for (int idx = tid; idx < Isz*HHALF; idx += SEQ_TPB) {
        int i = idx >> 6, c = idx & 63;
        float2 r = g_sab[i*Hsz + own_base + c];
        ssa[c*SSTR + i] = r.x;
        ssb[c*SSTR + i] = r.y;
        ssc[c*SSTR + i] = g_scs[i*Hsz + own_base + c];
    }
    // x double buffer: slot t&1 holds x[b, t]
    if (tid < Isz) {
        xbuf[tid]       = x[(b*Ssz + 0)*Isz + tid];
        xbuf[128 + tid] = (Ssz > 1) ? x[(b*Ssz + 1)*Isz + tid] : 0.f;
        vfin[tid] = h0[b*Hsz + tid];
    }

    // per-thread recurrent edge params: srcs j = base + e*8 + g (R7 scattered)
    float ao[8], bo[8], cso[8], ap[8], bp[8], csp[8];
    #pragma unroll
    for (int e = 0; e < 8; e++) {
        int jo = own_base  + e*8 + g;
        int jp = peer_base + e*8 + g;
        float2 r0 = g_rab[jo*Hsz + habs];
        float2 r1 = g_rab[jp*Hsz + habs];
        ao[e] = r0.x; bo[e] = r0.y; cso[e] = g_rcs[jo*Hsz + habs];
        ap[e] = r1.x; bp[e] = r1.y; csp[e] = g_rcs[jp*Hsz + habs];
    }
    float cmt  = g_cmt[habs];
    float ncst = g_numconst[habs];
    float dcst = g_denconst[habs];
    float aa2 = alpha_p[0] * amplitude[h2];
    float om2 = omega[h2];
    float pb2 = phase_b[h2];
    float bet = beta_p[0];

    if (tid == 0) mbar_init(mbar, 1);
    __syncthreads();
    asm volatile("barrier.cluster.arrive.aligned;" ::: "memory");
    asm volatile("barrier.cluster.wait.aligned;"   ::: "memory");

    uint32_t vfull_rm, mbar_rm;
    asm("mapa.shared::cluster.u32 %0, %1, %2;" : "=r"(vfull_rm) : "r"(sbase + OFF_VFULL), "r"(peerR));
    asm("mapa.shared::cluster.u32 %0, %1, %2;" : "=r"(mbar_rm)  : "r"(sbase + OFF_MBAR),  "r"(peerR));

    if (tid == 0) mbar_expect_tx(mbar, 256);

    #define EDGE_HALF(VPTR, BASE, A, B_, CS, N, D)                                  \
        _Pragma("unroll")                                                           \
        for (int e = 0; e < 8; e++) {                                               \
            float vv = (VPTR)[(BASE) + e*8 + g];                                    \
            float t = tanhap(fmaf((A)[e], vv, (B_)[e]));                            \
            N = fmaf((CS)[e], t, N);                                                \
            D = fmaf(fabsb((CS)[e]), t, D);                                         \
        }

    #define REDUCE_ND(N, D)                                                         \
        N += __shfl_xor_sync(0xffffffffu, N, 1);                                    \
        D += __shfl_xor_sync(0xffffffffu, D, 1);                                    \
        N += __shfl_xor_sync(0xffffffffu, N, 2);                                    \
        D += __shfl_xor_sync(0xffffffffu, D, 2);                                    \
        N += __shfl_xor_sync(0xffffffffu, N, 4);                                    \
        D += __shfl_xor_sync(0xffffffffu, D, 4);

    // one sensory eval: input i = c*8 + g (conflict-free smem pattern)
    #define SENS_EVAL(XB, c, SN, SD)                                                \
        {                                                                           \
            int i_ = (c)*8 + g;                                                     \
            float xv_ = (XB)[i_];                                                   \
            float t_ = tanhap(fmaf(ssa[hl*SSTR + i_], xv_, ssb[hl*SSTR + i_]));     \
            float cs_ = ssc[hl*SSTR + i_];                                          \
            SN = fmaf(cs_, t_, SN);                                                 \
            SD = fmaf(fabsb(cs_), t_, SD);                                          \
        }

    // ---- base[0]: direct sensory compute from x[0] ----
    float nb, db;
    {
        float sn = 0.f, sd = 0.f;
        #pragma unroll
        for (int c = 0; c < 16; c++) SENS_EVAL(xbuf, c, sn, sd)
        REDUCE_ND(sn, sd)
        nb = ncst + sn;
        db = dcst + sd;
    }

    float v;

    for (int s = 0; s < Ssz; s++) {
        // prefetch x[b, s+2] into register (staged to smem at epilogue)
        float xr = 0.f;
        int s2 = s + 2;
        if (tid < Isz && s2 < Ssz) xr = x[(b*Ssz + s2)*Isz + tid];

        const float* xb1 = xbuf + ((s + 1) & 1) * Isz;   // x[s+1] for base[s+1]
        float sn = 0.f, sd = 0.f;

        // ---- unfold 0: fully local ----
        v = vfin[habs];
        {
            float n = 0.f, d = 0.f;
            EDGE_HALF(vfin, own_base,  ao, bo, cso, n, d)
            EDGE_HALF(vfin, peer_base, ap, bp, csp, n, d)
            REDUCE_ND(n, d)
            v = __fdividef(fmaf(cmt, v, nb + n), db + d);
        }
        if (g == 0) vfull[habs] = v;
        __syncthreads();
        if (tid == 0)
            bulk_to_peer(vfull_rm + (uint32_t)own_base*4u,
                         sbase + OFF_VFULL + (uint32_t)own_base*4u, 256u, mbar_rm);

        // ---- unfolds 1..5, sensory chunks fill the exchange-wait windows ----
        #pragma unroll
        for (int u = 1; u < UNF; u++) {
            const int rslot = (u - 1) & 1;
            const int wslot = u & 1;
            const float* vf = vfull + rslot*Hsz;
            float n = 0.f, d = 0.f;
            EDGE_HALF(vf, own_base, ao, bo, cso, n, d)
            // sensory chunk (independent work) before the wait
            #pragma unroll
            for (int c = (u-1)*3; c < (u-1)*3 + 3; c++) SENS_EVAL(xb1, c, sn, sd)
            mbar_wait_cluster(mbar, (uint32_t)((s*UNF + u - 1) & 1));
            if (tid == 0) mbar_expect_tx(mbar, 256);
            EDGE_HALF(vf, peer_base, ap, bp, csp, n, d)
            REDUCE_ND(n, d)
            v = __fdividef(fmaf(cmt, v, nb + n), db + d);
            if (g == 0) vfull[wslot*Hsz + habs] = v;
            __syncthreads();
            if (tid == 0)
                bulk_to_peer(vfull_rm + (uint32_t)(wslot*512 + own_base*4),
                             sbase + OFF_VFULL + (uint32_t)(wslot*512 + own_base*4),
                             256u, mbar_rm);
        }

        // ---- epilogue ----
        SENS_EVAL(xb1, 15, sn, sd)
        mbar_wait_cluster(mbar, (uint32_t)((s*UNF + 5) & 1));
        if (tid == 0) mbar_expect_tx(mbar, 256);

        // finish base[s+1]
        REDUCE_ND(sn, sd)
        float nb_next = ncst + sn;
        float db_next = dcst + sd;

        const float* v6 = vfull + Hsz;                 // slot (UNF-1)&1 = 1
        const float2* v6f2 = (const float2*)v6;
        {
            float php = 0.f;
            #pragma unroll 8
            for (int i = 0; i < 16; i++) {
                int k2 = g2*16 + i;
                float2 wv = bf2f2(pwb[k2*Hsz + h2]);
                float2 v2 = v6f2[k2];
                php = fmaf(wv.x, v2.x, fmaf(wv.y, v2.y, php));
            }
            pph[g2*Hsz + h2] = php;
        }
        __syncthreads();
        float phi = pph[h2] + pph[Hsz + h2] + pph[2*Hsz + h2] + pph[3*Hsz + h2] + pb2;
        float vp  = v6[h2] + aa2 * __sinf(fmaf(om2, (float)s, phi));
        float sg  = fmaf(0.5f, tanhap(0.5f * vp), 0.5f);
        sgb[h2] = sg;                                  // 4 same-value writers, benign
        __syncthreads();
        {
            const float2* sgf2 = (const float2*)sgb;
            float accp = 0.f;
            #pragma unroll 8
            for (int i = 0; i < 16; i++) {
                int k2 = g2*16 + i;
                float2 wv = bf2f2(sab[k2*Hsz + h2]);
                float2 s2v = sgf2[k2];
                accp = fmaf(wv.x, s2v.x, fmaf(wv.y, s2v.y, accp));
            }
            psa[g2*Hsz + h2] = accp;
        }
        __syncthreads();
        if (g2 == 0) {
            float acc = psa[h2] + psa[Hsz + h2] + psa[2*Hsz + h2] + psa[3*Hsz + h2];
            float vfl = fmaf(bet, acc, vp);
            if (rank == 0) out[(b*Ssz + s)*Hsz + h2] = vfl;
            vfin[h2] = vfl;
        }
        // stage x[s+2] into its slot (slot s&1; not read during this step)
        if (tid < Isz && s2 < Ssz) xbuf[(s & 1)*Isz + tid] = xr;
        __syncthreads();

        nb = nb_next; db = db_next;
    }

    if (write_hfinal && g2 == 0 && rank == 0)
        out[Bsz*Ssz*Hsz + b*Hsz + h2] = vfin[h2];

    asm volatile("barrier.cluster.arrive.aligned;" ::: "memory");
    asm volatile("barrier.cluster.wait.aligned;"   ::: "memory");

    #undef EDGE_HALF
    #undef REDUCE_ND
    #undef SENS_EVAL
}

// ---------------- launch ----------------
extern "C" void kernel_launch(void* const* d_in, const int* in_sizes, int n_in,
                              void* d_out, int out_size)
{
    const float* x        = (const float*)d_in[0];
    const float* h0       = (const float*)d_in[1];
    const float* input_w  = (const float*)d_in[2];
    const float* input_b  = (const float*)d_in[3];
    const float* gleak    = (const float*)d_in[4];
    const float* vleak    = (const float*)d_in[5];
    const float* cm       = (const float*)d_in[6];
    const float* sigma    = (const float*)d_in[7];
    const float* mu       = (const float*)d_in[8];
    const float* w        = (const float*)d_in[9];
    const float* erev     = (const float*)d_in[10];
    const float* s_sigma  = (const float*)d_in[11];
    const float* s_mu     = (const float*)d_in[12];
    const float* s_w      = (const float*)d_in[13];
    const float* s_erev   = (const float*)d_in[14];
    const float* amplitude= (const float*)d_in[15];
    const float* omega    = (const float*)d_in[16];
    const float* phase_W  = (const float*)d_in[17];
    const float* phase_b  = (const float*)d_in[18];
    const float* alpha    = (const float*)d_in[19];
    const float* sa_W     = (const float*)d_in[20];
    const float* beta     = (const float*)d_in[21];
    float* out = (float*)d_out;

    cudaFuncSetAttribute(seq_kernel, cudaFuncAttributeMaxDynamicSharedMemorySize, SMEM_SEQ);

    prep_kernel<<<Hsz + Isz, Hsz>>>(sigma, mu, w, erev, s_sigma, s_mu, s_w, s_erev, input_w, input_b);
    prep2_kernel<<<1, Hsz>>>(gleak, vleak, cm, phase_W, sa_W);

    int whf = (out_size >= Bsz*Ssz*Hsz + Bsz*Hsz) ? 1 : 0;
    seq_kernel<<<Bsz*2, SEQ_TPB, SMEM_SEQ>>>(x, h0, amplitude, omega, phase_b, alpha, beta, out, whf);
}

// round 10
// speedup vs baseline: 1.1148x; 1.0744x over previous
#include <cuda_runtime.h>
#include <cuda_bf16.h>
#include <cstdint>

#define Bsz 64
#define Ssz 256
#define Isz 128
#define Hsz 128
#define UNF 6

#define SEQ_TPB 512
#define HHALF 64
#define SSTR 136    // floats per sensory row (bank-engineered)

// ---------------- device scratch ----------------
__device__ float2 g_rab[Hsz*Hsz];       // (a,b): a=0.5*sigma, b=-0.5*sigma*mu, [src][dst]
__device__ float  g_rcs[Hsz*Hsz];       // 0.5*softplus(w)*erev, [src][dst]
__device__ float2 g_sab[Isz*Hsz];       // sensory (a',b') with input affine folded, [i][h]
__device__ float  g_scs[Isz*Hsz];       // sensory signed weight, [i][h]
__device__ float  g_numconst[Hsz];
__device__ float  g_denconst[Hsz];
__device__ float  g_cmt[Hsz];
__device__ uint32_t g_pwB[(Hsz/2)*Hsz]; // phase_W bf16x2 packed: [k2][h]
__device__ uint32_t g_saB[(Hsz/2)*Hsz]; // sa_W    bf16x2 packed: [k2][h]

// ---------------- helpers ----------------
__device__ __forceinline__ float sp(float x) { return log1pf(expf(x)); }
__device__ __forceinline__ float tanhap(float x) {
    float y; asm("tanh.approx.f32 %0, %1;" : "=f"(y) : "f"(x)); return y;
}
__device__ __forceinline__ float fabsb(float x) {
    return __int_as_float(__float_as_int(x) & 0x7fffffff);
}
__device__ __forceinline__ float2 bf2f2(uint32_t u) {
    return __bfloat1622float2(*reinterpret_cast<__nv_bfloat162*>(&u));
}
__device__ __forceinline__ uint32_t smem_u32(const void* p) {
    uint32_t a; asm("{ .reg .u64 t; cvta.to.shared.u64 t, %1; cvt.u32.u64 %0, t; }" : "=r"(a) : "l"(p));
    return a;
}
__device__ __forceinline__ void mbar_init(uint32_t mbar, uint32_t cnt) {
    asm volatile("mbarrier.init.shared.b64 [%0], %1;" :: "r"(mbar), "r"(cnt) : "memory");
}
__device__ __forceinline__ void mbar_expect_tx(uint32_t mbar, uint32_t bytes) {
    asm volatile("mbarrier.arrive.expect_tx.shared.b64 _, [%0], %1;" :: "r"(mbar), "r"(bytes) : "memory");
}
__device__ __forceinline__ void mbar_wait_cluster(uint32_t mbar, uint32_t par) {
    asm volatile(
        "{\n\t.reg .pred P;\n"
        "WL_%=:\n\t"
        "mbarrier.try_wait.parity.acquire.cluster.shared::cta.b64 P, [%0], %1, 0x989680;\n\t"
        "@!P bra WL_%=;\n\t}"
        :: "r"(mbar), "r"(par) : "memory");
}
__device__ __forceinline__ void bulk_to_peer(uint32_t dst_cluster, uint32_t src_cta,
                                             uint32_t bytes, uint32_t mbar_cluster) {
    asm volatile("fence.proxy.async.shared::cta;" ::: "memory");
    asm volatile("cp.async.bulk.shared::cluster.shared::cta.mbarrier::complete_tx::bytes "
                 "[%0], [%1], %2, [%3];"
                 :: "r"(dst_cluster), "r"(src_cta), "r"(bytes), "r"(mbar_cluster) : "memory");
}

// ---------------- kernel A: per-edge param folding ----------------
__global__ void prep_kernel(const float* __restrict__ sigma, const float* __restrict__ mu,
                            const float* __restrict__ w,     const float* __restrict__ erev,
                            const float* __restrict__ s_sigma, const float* __restrict__ s_mu,
                            const float* __restrict__ s_w,   const float* __restrict__ s_erev,
                            const float* __restrict__ input_w, const float* __restrict__ input_b)
{
    int r = blockIdx.x, h = threadIdx.x;
    if (r < Hsz) {
        int idx = r*Hsz + h;
        float a = 0.5f * sigma[idx];
        g_rab[idx] = make_float2(a, -a * mu[idx]);
        g_rcs[idx] = 0.5f * sp(w[idx]) * erev[idx];
    } else {
        int i = r - Hsz;
        int idx = i*Hsz + h;
        float a = 0.5f * s_sigma[idx];
        g_sab[idx] = make_float2(a * input_w[i], a * (input_b[i] - s_mu[idx]));
        g_scs[idx] = 0.5f * sp(s_w[idx]) * s_erev[idx];
    }
}

// ---------------- kernel A2 ----------------
__global__ void prep2_kernel(const float* __restrict__ gleak, const float* __restrict__ vleak,
                             const float* __restrict__ cm,
                             const float* __restrict__ phase_W, const float* __restrict__ sa_W)
{
    int h = threadIdx.x;
    float nc = 0.f, dc = 0.f;
    for (int j = 0; j < Hsz; j++) { float cs = g_rcs[j*Hsz + h]; nc += cs; dc += fabsf(cs); }
    for (int i = 0; i < Isz; i++) { float cs = g_scs[i*Hsz + h]; nc += cs; dc += fabsf(cs); }
    float gl  = sp(gleak[h]);
    float cmt = sp(cm[h]) * (float)UNF;
    g_numconst[h] = gl * vleak[h] + nc;
    g_denconst[h] = cmt + gl + 1e-8f + dc;
    g_cmt[h] = cmt;
    for (int k2 = 0; k2 < Hsz/2; k2++) {
        __nv_bfloat162 p, q;
        p.x = __float2bfloat16(phase_W[h*Hsz + 2*k2]);
        p.y = __float2bfloat16(phase_W[h*Hsz + 2*k2 + 1]);
        q.x = __float2bfloat16(sa_W[h*Hsz + 2*k2]);
        q.y = __float2bfloat16(sa_W[h*Hsz + 2*k2 + 1]);
        g_pwB[k2*Hsz + h] = *reinterpret_cast<uint32_t*>(&p);
        g_saB[k2*Hsz + h] = *reinterpret_cast<uint32_t*>(&q);
    }
}

// ---------------- smem byte offsets for seq kernel ----------------
#define OFF_PWB    0                       // 32768
#define OFF_SAB    32768                   // 32768 -> 65536
#define OFF_SSA    65536                   // 64*136*4 = 34816 -> 100352
#define OFF_SSB    100352                  // 34816 -> 135168
#define OFF_SSC    135168                  // 34816 -> 169984
#define OFF_VFULL  169984                  // 2*128*4 = 1024 -> 171008
#define OFF_VFIN   171008                  // 512 -> 171520
#define OFF_PPH    171520                  // 2048 -> 173568
#define OFF_PSA    173568                  // 2048 -> 175616
#define OFF_SGB    175616                  // 512 -> 176128
#define OFF_XBUF   176128                  // 2*128*4 = 1024 -> 177152
#define OFF_MBAR   177152                  // 16
#define SMEM_SEQ   177280

// ---------------- kernel C: fused scan — window-filled ----------------
__global__ __launch_bounds__(SEQ_TPB, 1) __cluster_dims__(2, 1, 1)
void seq_kernel(const float* __restrict__ x, const float* __restrict__ h0,
                const float* __restrict__ amplitude, const float* __restrict__ omega,
                const float* __restrict__ phase_b, const float* __restrict__ alpha_p,
                const float* __restrict__ beta_p,
                float* __restrict__ out, int write_hfinal)
{
    extern __shared__ char smc[];
    uint32_t* pwb = (uint32_t*)(smc + OFF_PWB);   // [64][128] bf16x2
    uint32_t* sab = (uint32_t*)(smc + OFF_SAB);   // [64][128] bf16x2
    float* ssa    = (float*)(smc + OFF_SSA);      // [64][SSTR]
    float* ssb    = (float*)(smc + OFF_SSB);      // [64][SSTR]
    float* ssc    = (float*)(smc + OFF_SSC);      // [64][SSTR]
    float* vfull  = (float*)(smc + OFF_VFULL);    // [2][128]
    float* vfin   = (float*)(smc + OFF_VFIN);     // [128]
    float* pph    = (float*)(smc + OFF_PPH);      // [4][128]
    float* psa    = (float*)(smc + OFF_PSA);      // [4][128]
    float* sgb    = (float*)(smc + OFF_SGB);      // [128]
    float* xbuf   = (float*)(smc + OFF_XBUF);     // [2][128]

    uint32_t sbase = smem_u32(smc);
    uint32_t mbar  = sbase + OFF_MBAR;

    uint32_t rank; asm("mov.u32 %0, %%cluster_ctarank;" : "=r"(rank));
    uint32_t peerR = rank ^ 1u;
    int b = blockIdx.x >> 1;
    int own_base  = (int)rank * HHALF;
    int peer_base = (int)peerR * HHALF;

    int tid  = threadIdx.x;
    int lane = tid & 31;
    int warp = tid >> 5;
    int g    = lane & 7;                      // src subgroup 0..7
    int hl   = (warp << 2) | (lane >> 3);     // 0..63 local dst
    int habs = own_base + hl;
    int h2   = tid & 127;                     // epilogue: dst
    int g2   = tid >> 7;                      // epilogue: k quarter
    int own_q = ((g2 >> 1) == (int)rank);     // quarter in locally-produced v6 half?

    for (int idx = tid; idx < (Hsz/2)*Hsz; idx += SEQ_TPB) {
        pwb[idx] = g_pwB[idx];
        sab[idx] = g_saB[idx];
    }
    for (int idx = tid; idx < Isz*HHALF; idx += SEQ_TPB) {
        int i = idx >> 6, c = idx & 63;
        float2 r = g_sab[i*Hsz + own_base + c];
        ssa[c*SSTR + i] = r.x;
        ssb[c*SSTR + i] = r.y;
        ssc[c*SSTR + i] = g_scs[i*Hsz + own_base + c];
    }
    if (tid < Isz) {
        xbuf[tid]       = x[(b*Ssz + 0)*Isz + tid];
        xbuf[128 + tid] = (Ssz > 1) ? x[(b*Ssz + 1)*Isz + tid] : 0.f;
        vfin[tid] = h0[b*Hsz + tid];
    }

    float ao[8], bo[8], cso[8], ap[8], bp[8], csp[8];
    #pragma unroll
    for (int e = 0; e < 8; e++) {
        int jo = own_base  + e*8 + g;
        int jp = peer_base + e*8 + g;
        float2 r0 = g_rab[jo*Hsz + habs];
        float2 r1 = g_rab[jp*Hsz + habs];
        ao[e] = r0.x; bo[e] = r0.y; cso[e] = g_rcs[jo*Hsz + habs];
        ap[e] = r1.x; bp[e] = r1.y; csp[e] = g_rcs[jp*Hsz + habs];
    }
    float cmt  = g_cmt[habs];
    float ncst = g_numconst[habs];
    float dcst = g_denconst[habs];
    float aa2 = alpha_p[0] * amplitude[h2];
    float om2 = omega[h2];
    float pb2 = phase_b[h2];
    float bet = beta_p[0];

    if (tid == 0) mbar_init(mbar, 1);
    __syncthreads();
    asm volatile("barrier.cluster.arrive.aligned;" ::: "memory");
    asm volatile("barrier.cluster.wait.aligned;"   ::: "memory");

    uint32_t vfull_rm, mbar_rm;
    asm("mapa.shared::cluster.u32 %0, %1, %2;" : "=r"(vfull_rm) : "r"(sbase + OFF_VFULL), "r"(peerR));
    asm("mapa.shared::cluster.u32 %0, %1, %2;" : "=r"(mbar_rm)  : "r"(sbase + OFF_MBAR),  "r"(peerR));

    if (tid == 0) mbar_expect_tx(mbar, 256);

    #define EDGE_HALF(VPTR, BASE, A, B_, CS, N, D)                                  \
        _Pragma("unroll")                                                           \
        for (int e = 0; e < 8; e++) {                                               \
            float vv = (VPTR)[(BASE) + e*8 + g];                                    \
            float t = tanhap(fmaf((A)[e], vv, (B_)[e]));                            \
            N = fmaf((CS)[e], t, N);                                                \
            D = fmaf(fabsb((CS)[e]), t, D);                                         \
        }

    #define REDUCE_ND(N, D)                                                         \
        N += __shfl_xor_sync(0xffffffffu, N, 1);                                    \
        D += __shfl_xor_sync(0xffffffffu, D, 1);                                    \
        N += __shfl_xor_sync(0xffffffffu, N, 2);                                    \
        D += __shfl_xor_sync(0xffffffffu, D, 2);                                    \
        N += __shfl_xor_sync(0xffffffffu, N, 4);                                    \
        D += __shfl_xor_sync(0xffffffffu, D, 4);

    #define SENS_EVAL(XB, c, SN, SD)                                                \
        {                                                                           \
            int i_ = (c)*8 + g;                                                     \
            float xv_ = (XB)[i_];                                                   \
            float t_ = tanhap(fmaf(ssa[hl*SSTR + i_], xv_, ssb[hl*SSTR + i_]));     \
            float cs_ = ssc[hl*SSTR + i_];                                          \
            SN = fmaf(cs_, t_, SN);                                                 \
            SD = fmaf(fabsb(cs_), t_, SD);                                          \
        }

    // ---- base[0]: direct sensory compute from x[0] ----
    float nb, db;
    {
        float sn = 0.f, sd = 0.f;
        #pragma unroll
        for (int c = 0; c < 16; c++) SENS_EVAL(xbuf, c, sn, sd)
        REDUCE_ND(sn, sd)
        nb = ncst + sn;
        db = dcst + sd;
    }

    float v;

    for (int s = 0; s < Ssz; s++) {
        // prefetch x[b, s+2] (staged to smem at epilogue)
        float xr = 0.f;
        int s2 = s + 2;
        if (tid < Isz && s2 < Ssz) xr = x[(b*Ssz + s2)*Isz + tid];

        const float* xb1 = xbuf + ((s + 1) & 1) * Isz;   // x[s+1] for base[s+1]
        float sn = 0.f, sd = 0.f;

        // ---- unfold 0: fully local ----
        v = vfin[habs];
        {
            float n = 0.f, d = 0.f;
            EDGE_HALF(vfin, own_base,  ao, bo, cso, n, d)
            SENS_EVAL(xb1, 15, sn, sd)                      // filler (no wait here, pure ILP)
            EDGE_HALF(vfin, peer_base, ap, bp, csp, n, d)
            REDUCE_ND(n, d)
            v = __fdividef(fmaf(cmt, v, nb + n), db + d);
        }
        if (g == 0) vfull[habs] = v;
        __syncthreads();
        if (tid == 0)
            bulk_to_peer(vfull_rm + (uint32_t)own_base*4u,
                         sbase + OFF_VFULL + (uint32_t)own_base*4u, 256u, mbar_rm);

        // ---- unfolds 1..5: sensory chunks fill the post-BAR drain + wait windows ----
        #pragma unroll
        for (int u = 1; u < UNF; u++) {
            const int rslot = (u - 1) & 1;
            const int wslot = u & 1;
            const float* vf = vfull + rslot*Hsz;
            // 2 chunks right after the (defer-blocking) BAR of the previous phase
            SENS_EVAL(xb1, (u-1)*3,     sn, sd)
            SENS_EVAL(xb1, (u-1)*3 + 1, sn, sd)
            float n = 0.f, d = 0.f;
            EDGE_HALF(vf, own_base, ao, bo, cso, n, d)
            SENS_EVAL(xb1, (u-1)*3 + 2, sn, sd)             // 1 chunk before the wait
            mbar_wait_cluster(mbar, (uint32_t)((s*UNF + u - 1) & 1));
            if (tid == 0) mbar_expect_tx(mbar, 256);
            EDGE_HALF(vf, peer_base, ap, bp, csp, n, d)
            REDUCE_ND(n, d)
            v = __fdividef(fmaf(cmt, v, nb + n), db + d);
            if (g == 0) vfull[wslot*Hsz + habs] = v;
            __syncthreads();
            if (tid == 0)
                bulk_to_peer(vfull_rm + (uint32_t)(wslot*512 + own_base*4),
                             sbase + OFF_VFULL + (uint32_t)(wslot*512 + own_base*4),
                             256u, mbar_rm);
        }

        // ---- epilogue: fill final exchange window with sens-reduce + own-half phi ----
        const float* v6 = vfull + Hsz;                 // slot (UNF-1)&1 = 1
        const float2* v6f2 = (const float2*)v6;

        REDUCE_ND(sn, sd)                              // finish base[s+1] in the window
        float nb_next = ncst + sn;
        float db_next = dcst + sd;

        float php = 0.f;
        if (own_q) {                                   // own-half v6 is local (BAR'd above)
            #pragma unroll 8
            for (int i = 0; i < 16; i++) {
                int k2 = g2*16 + i;
                float2 wv = bf2f2(pwb[k2*Hsz + h2]);
                float2 v2 = v6f2[k2];
                php = fmaf(wv.x, v2.x, fmaf(wv.y, v2.y, php));
            }
        }
        mbar_wait_cluster(mbar, (uint32_t)((s*UNF + 5) & 1));
        if (tid == 0) mbar_expect_tx(mbar, 256);
        if (!own_q) {
            #pragma unroll 8
            for (int i = 0; i < 16; i++) {
                int k2 = g2*16 + i;
                float2 wv = bf2f2(pwb[k2*Hsz + h2]);
                float2 v2 = v6f2[k2];
                php = fmaf(wv.x, v2.x, fmaf(wv.y, v2.y, php));
            }
        }
        pph[g2*Hsz + h2] = php;
        __syncthreads();
        float phi = pph[h2] + pph[Hsz + h2] + pph[2*Hsz + h2] + pph[3*Hsz + h2] + pb2;
        float vp  = v6[h2] + aa2 * __sinf(fmaf(om2, (float)s, phi));
        float sg  = fmaf(0.5f, tanhap(0.5f * vp), 0.5f);
        sgb[h2] = sg;
        __syncthreads();
        {
            const float2* sgf2 = (const float2*)sgb;
            float accp = 0.f;
            #pragma unroll 8
            for (int i = 0; i < 16; i++) {
                int k2 = g2*16 + i;
                float2 wv = bf2f2(sab[k2*Hsz + h2]);
                float2 s2v = sgf2[k2];
                accp = fmaf(wv.x, s2v.x, fmaf(wv.y, s2v.y, accp));
            }
            psa[g2*Hsz + h2] = accp;
        }
        __syncthreads();
        if (g2 == 0) {
            float acc = psa[h2] + psa[Hsz + h2] + psa[2*Hsz + h2] + psa[3*Hsz + h2];
            float vfl = fmaf(bet, acc, vp);
            if (rank == 0) out[(b*Ssz + s)*Hsz + h2] = vfl;
            vfin[h2] = vfl;
        }
        if (tid < Isz && s2 < Ssz) xbuf[(s & 1)*Isz + tid] = xr;
        __syncthreads();

        nb = nb_next; db = db_next;
    }

    if (write_hfinal && g2 == 0 && rank == 0)
        out[Bsz*Ssz*Hsz + b*Hsz + h2] = vfin[h2];

    asm volatile("barrier.cluster.arrive.aligned;" ::: "memory");
    asm volatile("barrier.cluster.wait.aligned;"   ::: "memory");

    #undef EDGE_HALF
    #undef REDUCE_ND
    #undef SENS_EVAL
}

// ---------------- launch ----------------
extern "C" void kernel_launch(void* const* d_in, const int* in_sizes, int n_in,
                              void* d_out, int out_size)
{
    const float* x        = (const float*)d_in[0];
    const float* h0       = (const float*)d_in[1];
    const float* input_w  = (const float*)d_in[2];
    const float* input_b  = (const float*)d_in[3];
    const float* gleak    = (const float*)d_in[4];
    const float* vleak    = (const float*)d_in[5];
    const float* cm       = (const float*)d_in[6];
    const float* sigma    = (const float*)d_in[7];
    const float* mu       = (const float*)d_in[8];
    const float* w        = (const float*)d_in[9];
    const float* erev     = (const float*)d_in[10];
    const float* s_sigma  = (const float*)d_in[11];
    const float* s_mu     = (const float*)d_in[12];
    const float* s_w      = (const float*)d_in[13];
    const float* s_erev   = (const float*)d_in[14];
    const float* amplitude= (const float*)d_in[15];
    const float* omega    = (const float*)d_in[16];
    const float* phase_W  = (const float*)d_in[17];
    const float* phase_b  = (const float*)d_in[18];
    const float* alpha    = (const float*)d_in[19];
    const float* sa_W     = (const float*)d_in[20];
    const float* beta     = (const float*)d_in[21];
    float* out = (float*)d_out;

    cudaFuncSetAttribute(seq_kernel, cudaFuncAttributeMaxDynamicSharedMemorySize, SMEM_SEQ);

    prep_kernel<<<Hsz + Isz, Hsz>>>(sigma, mu, w, erev, s_sigma, s_mu, s_w, s_erev, input_w, input_b);
    prep2_kernel<<<1, Hsz>>>(gleak, vleak, cm, phase_W, sa_W);

    int whf = (out_size >= Bsz*Ssz*Hsz + Bsz*Hsz) ? 1 : 0;
    seq_kernel<<<Bsz*2, SEQ_TPB, SMEM_SEQ>>>(x, h0, amplitude, omega, phase_b, alpha, beta, out, whf);
}